// round 1
// baseline (speedup 1.0000x reference)
#include <cuda_runtime.h>
#include <math.h>

#define NTOK  16384
#define NHEAD 16
#define DHEAD 128
#define HID   512
#define DTOT  2048

// Scratch (allocation-free rule: __device__ globals)
static __device__ float g_rs[NTOK];
static __device__ float g_b0[(size_t)NHEAD * NTOK * HID];
static __device__ float g_b1[(size_t)NHEAD * NTOK * HID];

// ---------------------------------------------------------------------------
// RMSNorm row scale: rs[row] = rsqrt(mean(x^2) + eps)
// ---------------------------------------------------------------------------
__global__ void rms_kernel(const float* __restrict__ x, float* __restrict__ rs) {
    int row = blockIdx.x;
    const float4* xr = reinterpret_cast<const float4*>(x + (size_t)row * DTOT);
    float s = 0.f;
#pragma unroll
    for (int i = 0; i < 2; i++) {
        float4 v = xr[threadIdx.x + i * 256];
        s += v.x * v.x + v.y * v.y + v.z * v.z + v.w * v.w;
    }
#pragma unroll
    for (int o = 16; o; o >>= 1) s += __shfl_xor_sync(0xffffffffu, s, o);
    __shared__ float ws[8];
    if ((threadIdx.x & 31) == 0) ws[threadIdx.x >> 5] = s;
    __syncthreads();
    if (threadIdx.x == 0) {
        float t = 0.f;
#pragma unroll
        for (int i = 0; i < 8; i++) t += ws[i];
        rs[row] = rsqrtf(t * (1.0f / DTOT) + 1.1920929e-7f);
    }
}

// ---------------------------------------------------------------------------
// Packed f32x2 helpers (PTX-only path; ptxas never emits FFMA2 from C++)
// ---------------------------------------------------------------------------
__device__ __forceinline__ unsigned long long splat2(float x) {
    unsigned long long r;
    asm("mov.b64 %0, {%1,%1};" : "=l"(r) : "f"(x));
    return r;
}
__device__ __forceinline__ void ffma2(unsigned long long& d,
                                      unsigned long long a,
                                      unsigned long long b) {
    asm("fma.rn.f32x2 %0, %1, %2, %0;" : "+l"(d) : "l"(a), "l"(b));
}
__device__ __forceinline__ float gelu_f(float x) {
    // exact gelu: x * 0.5 * (1 + erf(x / sqrt(2)))
    return 0.5f * x * (1.0f + erff(x * 0.70710678118654752f));
}

// ---------------------------------------------------------------------------
// Batched per-head SGEMM: C[h] = (opt gelu)( A[h] @ W[h] )
//   BM=BN=128, BK=8, 256 threads, 8x8 per thread, packed f32x2 FMA.
//   SCALE: layer-0 only — fold rmsnorm row scale and RMSNorm weight g into A.
//   GELU:  apply exact gelu in the epilogue (layers 0,1,2).
// grid = (M/128, N/128, NHEAD)
// ---------------------------------------------------------------------------
template <bool GELU, bool SCALE>
__global__ __launch_bounds__(256, 2) void sgemm_kernel(
    const float* __restrict__ A, size_t aHeadStride, int lda,
    const float* __restrict__ W, int K, int N,
    float* __restrict__ C, size_t cHeadStride, int ldc,
    const float* __restrict__ rs, const float* __restrict__ gw)
{
    const int h = blockIdx.z;
    A += (size_t)h * aHeadStride;
    W += (size_t)h * (size_t)K * N;
    C += (size_t)h * cHeadStride;
    if (SCALE) gw += h * DHEAD;

    __shared__ float As[8][132];   // padded: conflict-free transposed stores
    __shared__ float Bs[8][128];

    const int tid = threadIdx.x;
    const int tx  = tid & 15;
    const int ty  = tid >> 4;

    const int aRow = tid >> 1;
    const int aCol = (tid & 1) * 4;
    const int bRow = tid >> 5;
    const int bCol = (tid & 31) * 4;

    const int gRow = blockIdx.x * 128 + aRow;
    const float rscale = SCALE ? rs[gRow] : 1.0f;
    const float* Aptr = A + (size_t)gRow * lda + aCol;
    const float* Wptr = W + (size_t)bRow * N + blockIdx.y * 128 + bCol;

    unsigned long long acc[8][4];
#pragma unroll
    for (int i = 0; i < 8; i++)
#pragma unroll
        for (int j = 0; j < 4; j++) acc[i][j] = 0ull;

    const int KT = K >> 3;
    for (int kt = 0; kt < KT; kt++) {
        float4 av = *reinterpret_cast<const float4*>(Aptr + kt * 8);
        if (SCALE) {
            av.x *= rscale * gw[kt * 8 + aCol + 0];
            av.y *= rscale * gw[kt * 8 + aCol + 1];
            av.z *= rscale * gw[kt * 8 + aCol + 2];
            av.w *= rscale * gw[kt * 8 + aCol + 3];
        }
        As[aCol + 0][aRow] = av.x;
        As[aCol + 1][aRow] = av.y;
        As[aCol + 2][aRow] = av.z;
        As[aCol + 3][aRow] = av.w;
        *reinterpret_cast<float4*>(&Bs[bRow][bCol]) =
            *reinterpret_cast<const float4*>(Wptr + (size_t)kt * 8 * N);
        __syncthreads();

#pragma unroll
        for (int k = 0; k < 8; k++) {
            float4 a0 = *reinterpret_cast<const float4*>(&As[k][ty * 8]);
            float4 a1 = *reinterpret_cast<const float4*>(&As[k][ty * 8 + 4]);
            ulonglong2 bq0 = *reinterpret_cast<const ulonglong2*>(&Bs[k][tx * 8]);
            ulonglong2 bq1 = *reinterpret_cast<const ulonglong2*>(&Bs[k][tx * 8 + 4]);
            unsigned long long ap[8] = {
                splat2(a0.x), splat2(a0.y), splat2(a0.z), splat2(a0.w),
                splat2(a1.x), splat2(a1.y), splat2(a1.z), splat2(a1.w)};
            unsigned long long bp[4] = {bq0.x, bq0.y, bq1.x, bq1.y};
#pragma unroll
            for (int i = 0; i < 8; i++)
#pragma unroll
                for (int j = 0; j < 4; j++) ffma2(acc[i][j], ap[i], bp[j]);
        }
        __syncthreads();
    }

    // Epilogue
#pragma unroll
    for (int i = 0; i < 8; i++) {
        float vals[8];
#pragma unroll
        for (int j = 0; j < 4; j++) {
            float2 v = *reinterpret_cast<float2*>(&acc[i][j]);
            vals[j * 2]     = v.x;
            vals[j * 2 + 1] = v.y;
        }
        if (GELU) {
#pragma unroll
            for (int j = 0; j < 8; j++) vals[j] = gelu_f(vals[j]);
        }
        size_t row = (size_t)blockIdx.x * 128 + ty * 8 + i;
        size_t col = (size_t)blockIdx.y * 128 + tx * 8;
        float4* cp = reinterpret_cast<float4*>(C + row * ldc + col);
        cp[0] = make_float4(vals[0], vals[1], vals[2], vals[3]);
        cp[1] = make_float4(vals[4], vals[5], vals[6], vals[7]);
    }
}

// ---------------------------------------------------------------------------
// kernel_launch: rmsnorm scale -> 4 batched GEMMs with fused gelu
// Inputs (metadata order): x, g, w0, w1, w2, w3
// ---------------------------------------------------------------------------
extern "C" void kernel_launch(void* const* d_in, const int* in_sizes, int n_in,
                              void* d_out, int out_size) {
    const float* x  = (const float*)d_in[0];
    const float* g  = (const float*)d_in[1];
    const float* w0 = (const float*)d_in[2];
    const float* w1 = (const float*)d_in[3];
    const float* w2 = (const float*)d_in[4];
    const float* w3 = (const float*)d_in[5];
    float* out = (float*)d_out;

    float *rs, *b0, *b1;
    cudaGetSymbolAddress((void**)&rs, g_rs);
    cudaGetSymbolAddress((void**)&b0, g_b0);
    cudaGetSymbolAddress((void**)&b1, g_b1);

    rms_kernel<<<NTOK, 256>>>(x, rs);

    dim3 blk(256);
    dim3 g512(NTOK / 128, HID / 128, NHEAD);
    dim3 g128(NTOK / 128, DHEAD / 128, NHEAD);

    // L0: t0 = gelu( (x * rs * g)[:,h] @ w0[h] )
    sgemm_kernel<true, true><<<g512, blk>>>(
        x, (size_t)DHEAD, DTOT, w0, DHEAD, HID,
        b0, (size_t)NTOK * HID, HID, rs, g);
    // L1: t1 = gelu( t0 @ w1[h] )
    sgemm_kernel<true, false><<<g512, blk>>>(
        b0, (size_t)NTOK * HID, HID, w1, HID, HID,
        b1, (size_t)NTOK * HID, HID, nullptr, nullptr);
    // L2: t2 = gelu( t1 @ w2[h] )
    sgemm_kernel<true, false><<<g512, blk>>>(
        b1, (size_t)NTOK * HID, HID, w2, HID, HID,
        b0, (size_t)NTOK * HID, HID, nullptr, nullptr);
    // L3: out[:,h] = t2 @ w3[h]   (no gelu)
    sgemm_kernel<false, false><<<g128, blk>>>(
        b0, (size_t)NTOK * HID, HID, w3, HID, DHEAD,
        out, (size_t)DHEAD, DTOT, nullptr, nullptr);
}

// round 3
// speedup vs baseline: 2.0337x; 2.0337x over previous
#include <cuda_runtime.h>
#include <cuda_bf16.h>
#include <math.h>
#include <stdint.h>

#define NTOK  16384
#define NHEAD 16
#define DHEAD 128
#define HID   512
#define DTOT  2048

typedef __nv_bfloat16 bf16;

// ---------------- scratch (device globals; no allocs allowed) ----------------
static __device__ bf16 g_xh[(size_t)NTOK * DTOT];
static __device__ bf16 g_xl[(size_t)NTOK * DTOT];
static __device__ bf16 g_ah[(size_t)NHEAD * NTOK * HID];
static __device__ bf16 g_al[(size_t)NHEAD * NTOK * HID];
static __device__ bf16 g_bh[(size_t)NHEAD * NTOK * HID];
static __device__ bf16 g_bl[(size_t)NHEAD * NTOK * HID];
static __device__ bf16 g_w0h[(size_t)NHEAD * HID * DHEAD];
static __device__ bf16 g_w0l[(size_t)NHEAD * HID * DHEAD];
static __device__ bf16 g_w1h[(size_t)NHEAD * HID * HID];
static __device__ bf16 g_w1l[(size_t)NHEAD * HID * HID];
static __device__ bf16 g_w2h[(size_t)NHEAD * HID * HID];
static __device__ bf16 g_w2l[(size_t)NHEAD * HID * HID];
static __device__ bf16 g_w3h[(size_t)NHEAD * DHEAD * HID];
static __device__ bf16 g_w3l[(size_t)NHEAD * DHEAD * HID];

// ---------------- helpers ----------------
__device__ __forceinline__ uint32_t smem_u32(const void* p) {
    uint32_t a;
    asm("{ .reg .u64 t; cvta.to.shared.u64 t, %1; cvt.u32.u64 %0, t; }"
        : "=r"(a) : "l"(p));
    return a;
}
__device__ __forceinline__ float gelu_f(float x) {
    return 0.5f * x * (1.0f + erff(x * 0.70710678118654752f));
}
__device__ __forceinline__ void split2(float v, bf16& hi, bf16& lo) {
    hi = __float2bfloat16_rn(v);
    lo = __float2bfloat16_rn(v - __bfloat162float(hi));
}
__device__ __forceinline__ uint32_t packbf(bf16 a, bf16 b) {
    return (uint32_t)__bfloat16_as_ushort(a) | ((uint32_t)__bfloat16_as_ushort(b) << 16);
}

__device__ __forceinline__ void ldsm4(uint32_t (&r)[4], uint32_t addr) {
    asm volatile("ldmatrix.sync.aligned.m8n8.x4.shared.b16 {%0,%1,%2,%3}, [%4];"
                 : "=r"(r[0]), "=r"(r[1]), "=r"(r[2]), "=r"(r[3]) : "r"(addr));
}
__device__ __forceinline__ void mma16816(float (&d)[4], const uint32_t (&a)[4],
                                         uint32_t b0, uint32_t b1) {
    asm volatile(
        "mma.sync.aligned.m16n8k16.row.col.f32.bf16.bf16.f32 "
        "{%0,%1,%2,%3}, {%4,%5,%6,%7}, {%8,%9}, {%0,%1,%2,%3};"
        : "+f"(d[0]), "+f"(d[1]), "+f"(d[2]), "+f"(d[3])
        : "r"(a[0]), "r"(a[1]), "r"(a[2]), "r"(a[3]), "r"(b0), "r"(b1));
}

// cp.async 16B tile loader: ROWS x 64 bf16 (128B rows), XOR-8 chunk swizzle
template <int ROWS>
__device__ __forceinline__ void ldt(uint32_t sbase, const bf16* g, int ldg_, int tid) {
#pragma unroll
    for (int q = tid; q < ROWS * 8; q += 256) {
        int r = q >> 3, c8 = q & 7;
        uint32_t dst = sbase + r * 128 + ((c8 ^ (r & 7)) << 4);
        const char* src = (const char*)(g + (size_t)r * ldg_) + c8 * 16;
        asm volatile("cp.async.cg.shared.global [%0], [%1], 16;"
                     :: "r"(dst), "l"(src) : "memory");
    }
}

// =======================================================================
// HMMA split-bf16 GEMM: D[128 x 128] = (Ahi+Alo)[128 x K] @ (Bhi+Blo)^T
// A: [M x K] (lda), B: [N x K] K-major. 3 MMA terms: AhBh + AlBh + AhBl.
// MODE 0: gelu -> split -> (Ch, Cl) bf16.  MODE 1: raw fp32 -> Cf.
// grid = (M/128, N/128, NHEAD), 256 threads.
// =======================================================================
template <int MODE>
__global__ __launch_bounds__(256, 1)
void hgemm_kernel(const bf16* __restrict__ Ah, const bf16* __restrict__ Al,
                  size_t aHead, int lda,
                  const bf16* __restrict__ Bh, const bf16* __restrict__ Bl,
                  size_t bHead, int K,
                  bf16* __restrict__ Ch, bf16* __restrict__ Cl,
                  float* __restrict__ Cf, size_t cHead, int ldc) {
    extern __shared__ char smem[];
    const uint32_t sb = smem_u32(smem);
    const int tid = threadIdx.x, wid = tid >> 5, lane = tid & 31;
    const int h = blockIdx.z;
    const int m0 = blockIdx.x * 128;
    const int n0 = blockIdx.y * 128;

    // stage layout: Ah[128][128B] Al Bh Bl -> 64KB per stage, 2 stages
    constexpr uint32_t TILE = 128 * 128;       // 16KB
    constexpr uint32_t STAGE = 4 * TILE;       // 64KB

    const bf16* gAh = Ah + h * aHead + (size_t)m0 * lda;
    const bf16* gAl = Al + h * aHead + (size_t)m0 * lda;
    const bf16* gBh = Bh + h * bHead + (size_t)n0 * K;
    const bf16* gBl = Bl + h * bHead + (size_t)n0 * K;

    // warp tile: 64(M) x 32(N); warp grid 2 x 4
    const int wm = (wid & 1) * 64;
    const int wn = (wid >> 1) * 32;

    // ldmatrix source rows (per-thread)
    int arow[4], brow[2];
#pragma unroll
    for (int mi = 0; mi < 4; mi++) arow[mi] = wm + mi * 16 + (lane & 15);
#pragma unroll
    for (int bj = 0; bj < 2; bj++)
        brow[bj] = wn + bj * 16 + ((lane >> 3) & 1) * 8 + (lane & 7);
    const int hi16 = lane >> 4;   // k-halve selector for x4 loads

    float acc[4][4][4];
#pragma unroll
    for (int i = 0; i < 4; i++)
#pragma unroll
        for (int j = 0; j < 4; j++)
#pragma unroll
            for (int e = 0; e < 4; e++) acc[i][j][e] = 0.f;

    const int KT = K >> 6;

    // preload stage 0
    ldt<128>(sb, gAh, lda, tid);
    ldt<128>(sb + TILE, gAl, lda, tid);
    ldt<128>(sb + 2 * TILE, gBh, K, tid);
    ldt<128>(sb + 3 * TILE, gBl, K, tid);
    asm volatile("cp.async.commit_group;" ::: "memory");

    for (int c = 0; c < KT; c++) {
        const uint32_t st = sb + (uint32_t)(c & 1) * STAGE;
        if (c + 1 < KT) {
            const uint32_t sn = sb + (uint32_t)((c + 1) & 1) * STAGE;
            const int k0 = (c + 1) * 64;
            ldt<128>(sn, gAh + k0, lda, tid);
            ldt<128>(sn + TILE, gAl + k0, lda, tid);
            ldt<128>(sn + 2 * TILE, gBh + k0, K, tid);
            ldt<128>(sn + 3 * TILE, gBl + k0, K, tid);
            asm volatile("cp.async.commit_group;" ::: "memory");
            asm volatile("cp.async.wait_group 1;" ::: "memory");
        } else {
            asm volatile("cp.async.wait_group 0;" ::: "memory");
        }
        __syncthreads();

#pragma unroll
        for (int s = 0; s < 4; s++) {
            uint32_t ahf[4][4], alf[4][4], bhf[2][4], blf[2][4];
            const int c2 = s * 2 + hi16;
#pragma unroll
            for (int mi = 0; mi < 4; mi++) {
                const uint32_t ao = arow[mi] * 128 + ((c2 ^ (arow[mi] & 7)) << 4);
                ldsm4(ahf[mi], st + ao);
                ldsm4(alf[mi], st + TILE + ao);
            }
#pragma unroll
            for (int bj = 0; bj < 2; bj++) {
                const uint32_t bo = brow[bj] * 128 + ((c2 ^ (brow[bj] & 7)) << 4);
                ldsm4(bhf[bj], st + 2 * TILE + bo);
                ldsm4(blf[bj], st + 3 * TILE + bo);
            }
            // term 1: Ah * Bh
#pragma unroll
            for (int mi = 0; mi < 4; mi++)
#pragma unroll
                for (int bj = 0; bj < 2; bj++) {
                    mma16816(acc[mi][2 * bj],     ahf[mi], bhf[bj][0], bhf[bj][2]);
                    mma16816(acc[mi][2 * bj + 1], ahf[mi], bhf[bj][1], bhf[bj][3]);
                }
            // term 2: Al * Bh
#pragma unroll
            for (int mi = 0; mi < 4; mi++)
#pragma unroll
                for (int bj = 0; bj < 2; bj++) {
                    mma16816(acc[mi][2 * bj],     alf[mi], bhf[bj][0], bhf[bj][2]);
                    mma16816(acc[mi][2 * bj + 1], alf[mi], bhf[bj][1], bhf[bj][3]);
                }
            // term 3: Ah * Bl
#pragma unroll
            for (int mi = 0; mi < 4; mi++)
#pragma unroll
                for (int bj = 0; bj < 2; bj++) {
                    mma16816(acc[mi][2 * bj],     ahf[mi], blf[bj][0], blf[bj][2]);
                    mma16816(acc[mi][2 * bj + 1], ahf[mi], blf[bj][1], blf[bj][3]);
                }
        }
        __syncthreads();
    }

    // ---------------- epilogue ----------------
    const int rbase = (lane >> 2);       // row within atom
    const int cbase = (lane & 3) * 2;    // col pair within n8

#pragma unroll
    for (int mi = 0; mi < 4; mi++) {
#pragma unroll
        for (int nj = 0; nj < 4; nj++) {
#pragma unroll
            for (int half = 0; half < 2; half++) {
                const size_t m = (size_t)m0 + wm + mi * 16 + rbase + half * 8;
                const int col = n0 + wn + nj * 8 + cbase;
                float v0 = acc[mi][nj][2 * half];
                float v1 = acc[mi][nj][2 * half + 1];
                if (MODE == 0) {
                    v0 = gelu_f(v0);
                    v1 = gelu_f(v1);
                    bf16 h0, l0, h1, l1;
                    split2(v0, h0, l0);
                    split2(v1, h1, l1);
                    *reinterpret_cast<uint32_t*>(Ch + h * cHead + m * ldc + col) =
                        packbf(h0, h1);
                    *reinterpret_cast<uint32_t*>(Cl + h * cHead + m * ldc + col) =
                        packbf(l0, l1);
                } else {
                    *reinterpret_cast<float2*>(Cf + h * cHead + m * ldc + col) =
                        make_float2(v0, v1);
                }
            }
        }
    }
}

// ---------------- RMSNorm + hi/lo split of x ----------------
__global__ void rms_split_kernel(const float* __restrict__ x, const float* __restrict__ g,
                                 bf16* __restrict__ xh, bf16* __restrict__ xl) {
    const int row = blockIdx.x, tid = threadIdx.x;
    const float4* xr = reinterpret_cast<const float4*>(x + (size_t)row * DTOT);
    float4 a = xr[tid], b = xr[tid + 256];
    float s = a.x * a.x + a.y * a.y + a.z * a.z + a.w * a.w +
              b.x * b.x + b.y * b.y + b.z * b.z + b.w * b.w;
#pragma unroll
    for (int o = 16; o; o >>= 1) s += __shfl_xor_sync(0xffffffffu, s, o);
    __shared__ float ws[8];
    __shared__ float srs;
    if ((tid & 31) == 0) ws[tid >> 5] = s;
    __syncthreads();
    if (tid == 0) {
        float t = 0.f;
#pragma unroll
        for (int i = 0; i < 8; i++) t += ws[i];
        srs = rsqrtf(t * (1.0f / DTOT) + 1.1920929e-7f);
    }
    __syncthreads();
    const float rs = srs;
    const float4* gr = reinterpret_cast<const float4*>(g);
    float4 ga = gr[tid], gb = gr[tid + 256];

    float va[8] = {a.x * rs * ga.x, a.y * rs * ga.y, a.z * rs * ga.z, a.w * rs * ga.w,
                   b.x * rs * gb.x, b.y * rs * gb.y, b.z * rs * gb.z, b.w * rs * gb.w};
    size_t base = (size_t)row * DTOT;
#pragma unroll
    for (int half = 0; half < 2; half++) {
        size_t o = base + (size_t)(tid + half * 256) * 4;
        uint32_t hp[2], lp[2];
#pragma unroll
        for (int j = 0; j < 2; j++) {
            bf16 h0, l0, h1, l1;
            split2(va[half * 4 + 2 * j], h0, l0);
            split2(va[half * 4 + 2 * j + 1], h1, l1);
            hp[j] = packbf(h0, h1);
            lp[j] = packbf(l0, l1);
        }
        *reinterpret_cast<uint2*>(xh + o) = make_uint2(hp[0], hp[1]);
        *reinterpret_cast<uint2*>(xl + o) = make_uint2(lp[0], lp[1]);
    }
}

// ---------------- weight transpose + hi/lo split: W[h][K][N] -> O[h][N][K] ----------------
__global__ void wsplit_kernel(const float* __restrict__ W, int K, int N,
                              bf16* __restrict__ Oh, bf16* __restrict__ Ol) {
    __shared__ float t[32][33];
    const int h = blockIdx.z;
    const int k0 = blockIdx.x * 32, n0 = blockIdx.y * 32;
    const int tx = threadIdx.x & 31, ty = threadIdx.x >> 5;
    const float* Wb = W + (size_t)h * K * N;
#pragma unroll
    for (int i = 0; i < 4; i++)
        t[ty + i * 8][tx] = Wb[(size_t)(k0 + ty + i * 8) * N + n0 + tx];
    __syncthreads();
#pragma unroll
    for (int i = 0; i < 4; i++) {
        int n = n0 + ty + i * 8, k = k0 + tx;
        float v = t[tx][ty + i * 8];
        bf16 hi, lo;
        split2(v, hi, lo);
        size_t o = ((size_t)h * N + n) * K + k;
        Oh[o] = hi;
        Ol[o] = lo;
    }
}

// ---------------- launch ----------------
extern "C" void kernel_launch(void* const* d_in, const int* in_sizes, int n_in,
                              void* d_out, int out_size) {
    const float* x  = (const float*)d_in[0];
    const float* g  = (const float*)d_in[1];
    const float* w0 = (const float*)d_in[2];
    const float* w1 = (const float*)d_in[3];
    const float* w2 = (const float*)d_in[4];
    const float* w3 = (const float*)d_in[5];
    float* out = (float*)d_out;

    bf16 *xh, *xl, *ah, *al, *bh, *bl;
    bf16 *w0h, *w0l, *w1h, *w1l, *w2h, *w2l, *w3h, *w3l;
    cudaGetSymbolAddress((void**)&xh, g_xh);
    cudaGetSymbolAddress((void**)&xl, g_xl);
    cudaGetSymbolAddress((void**)&ah, g_ah);
    cudaGetSymbolAddress((void**)&al, g_al);
    cudaGetSymbolAddress((void**)&bh, g_bh);
    cudaGetSymbolAddress((void**)&bl, g_bl);
    cudaGetSymbolAddress((void**)&w0h, g_w0h);
    cudaGetSymbolAddress((void**)&w0l, g_w0l);
    cudaGetSymbolAddress((void**)&w1h, g_w1h);
    cudaGetSymbolAddress((void**)&w1l, g_w1l);
    cudaGetSymbolAddress((void**)&w2h, g_w2h);
    cudaGetSymbolAddress((void**)&w2l, g_w2l);
    cudaGetSymbolAddress((void**)&w3h, g_w3h);
    cudaGetSymbolAddress((void**)&w3l, g_w3l);

    constexpr int SMEM = 2 * 4 * 128 * 128;  // 131072
    cudaFuncSetAttribute(hgemm_kernel<0>,
                         cudaFuncAttributeMaxDynamicSharedMemorySize, SMEM);
    cudaFuncSetAttribute(hgemm_kernel<1>,
                         cudaFuncAttributeMaxDynamicSharedMemorySize, SMEM);

    // prep
    rms_split_kernel<<<NTOK, 256>>>(x, g, xh, xl);
    wsplit_kernel<<<dim3(DHEAD / 32, HID / 32, NHEAD), 256>>>(w0, DHEAD, HID, w0h, w0l);
    wsplit_kernel<<<dim3(HID / 32, HID / 32, NHEAD), 256>>>(w1, HID, HID, w1h, w1l);
    wsplit_kernel<<<dim3(HID / 32, HID / 32, NHEAD), 256>>>(w2, HID, HID, w2h, w2l);
    wsplit_kernel<<<dim3(HID / 32, DHEAD / 32, NHEAD), 256>>>(w3, HID, DHEAD, w3h, w3l);

    const size_t actHead = (size_t)NTOK * HID;

    // L0: a = gelu( xn[:,h] @ w0[h] )
    hgemm_kernel<0><<<dim3(NTOK / 128, HID / 128, NHEAD), 256, SMEM>>>(
        xh, xl, (size_t)DHEAD, DTOT, w0h, w0l, (size_t)HID * DHEAD, DHEAD,
        ah, al, nullptr, actHead, HID);
    // L1: b = gelu( a @ w1[h] )
    hgemm_kernel<0><<<dim3(NTOK / 128, HID / 128, NHEAD), 256, SMEM>>>(
        ah, al, actHead, HID, w1h, w1l, (size_t)HID * HID, HID,
        bh, bl, nullptr, actHead, HID);
    // L2: a = gelu( b @ w2[h] )
    hgemm_kernel<0><<<dim3(NTOK / 128, HID / 128, NHEAD), 256, SMEM>>>(
        bh, bl, actHead, HID, w2h, w2l, (size_t)HID * HID, HID,
        ah, al, nullptr, actHead, HID);
    // L3: out[:,h] = a @ w3[h]   (fp32, no gelu)
    hgemm_kernel<1><<<dim3(NTOK / 128, DHEAD / 128, NHEAD), 256, SMEM>>>(
        ah, al, actHead, HID, w3h, w3l, (size_t)DHEAD * HID, HID,
        nullptr, nullptr, out, (size_t)DHEAD, DTOT);
}

// round 4
// speedup vs baseline: 3.1857x; 1.5664x over previous
#include <cuda_runtime.h>
#include <cuda_fp16.h>
#include <math.h>
#include <stdint.h>

#define NTOK  16384
#define NHEAD 16
#define DHEAD 128
#define HID   512
#define DTOT  2048

typedef __half fh;

// ---------------- scratch (device globals; no allocs allowed) ----------------
static __device__ fh g_xh[(size_t)NTOK * DTOT];
static __device__ fh g_xl[(size_t)NTOK * DTOT];
static __device__ fh g_ah[(size_t)NHEAD * NTOK * HID];
static __device__ fh g_al[(size_t)NHEAD * NTOK * HID];
static __device__ fh g_bh[(size_t)NHEAD * NTOK * HID];
static __device__ fh g_bl[(size_t)NHEAD * NTOK * HID];
static __device__ fh g_w0[(size_t)NHEAD * HID * DHEAD];
static __device__ fh g_w1[(size_t)NHEAD * HID * HID];
static __device__ fh g_w2[(size_t)NHEAD * HID * HID];
static __device__ fh g_w3[(size_t)NHEAD * DHEAD * HID];

// ---------------- helpers ----------------
__device__ __forceinline__ uint32_t smem_u32(const void* p) {
    uint32_t a;
    asm("{ .reg .u64 t; cvta.to.shared.u64 t, %1; cvt.u32.u64 %0, t; }"
        : "=r"(a) : "l"(p));
    return a;
}
__device__ __forceinline__ float gelu_f(float x) {
    return 0.5f * x * (1.0f + erff(x * 0.70710678118654752f));
}
__device__ __forceinline__ void split2h(float v, fh& hi, fh& lo) {
    hi = __float2half_rn(v);
    lo = __float2half_rn(v - __half2float(hi));
}
__device__ __forceinline__ uint32_t packh(fh a, fh b) {
    return (uint32_t)__half_as_ushort(a) | ((uint32_t)__half_as_ushort(b) << 16);
}

__device__ __forceinline__ void ldsm4(uint32_t (&r)[4], uint32_t addr) {
    asm volatile("ldmatrix.sync.aligned.m8n8.x4.shared.b16 {%0,%1,%2,%3}, [%4];"
                 : "=r"(r[0]), "=r"(r[1]), "=r"(r[2]), "=r"(r[3]) : "r"(addr));
}
__device__ __forceinline__ void mma16816(float (&d)[4], const uint32_t (&a)[4],
                                         uint32_t b0, uint32_t b1) {
    asm volatile(
        "mma.sync.aligned.m16n8k16.row.col.f32.f16.f16.f32 "
        "{%0,%1,%2,%3}, {%4,%5,%6,%7}, {%8,%9}, {%0,%1,%2,%3};"
        : "+f"(d[0]), "+f"(d[1]), "+f"(d[2]), "+f"(d[3])
        : "r"(a[0]), "r"(a[1]), "r"(a[2]), "r"(a[3]), "r"(b0), "r"(b1));
}

// cp.async 16B tile loader: ROWS x 64 fp16 (128B rows), XOR-8 chunk swizzle
template <int ROWS>
__device__ __forceinline__ void ldt(uint32_t sbase, const fh* g, int ldg_, int tid) {
#pragma unroll
    for (int q = tid; q < ROWS * 8; q += 256) {
        int r = q >> 3, c8 = q & 7;
        uint32_t dst = sbase + r * 128 + ((c8 ^ (r & 7)) << 4);
        const char* src = (const char*)(g + (size_t)r * ldg_) + c8 * 16;
        asm volatile("cp.async.cg.shared.global [%0], [%1], 16;"
                     :: "r"(dst), "l"(src) : "memory");
    }
}

// =======================================================================
// HMMA fp16 2-term GEMM: D[128x128] = (Ahi+Alo)[128xK] @ Bh[128xK]^T
// A split into fp16 hi/lo (22-bit capture); B single fp16 (weights).
// MODE 0: gelu -> split -> (Ch, Cl) fp16.  MODE 1: raw fp32 -> Cf.
// grid = (M/128, N/128, NHEAD), 256 threads, 2 CTAs/SM.
// =======================================================================
template <int MODE>
__global__ __launch_bounds__(256, 2)
void hgemm_kernel(const fh* __restrict__ Ah, const fh* __restrict__ Al,
                  size_t aHead, int lda,
                  const fh* __restrict__ Bh, size_t bHead, int K,
                  fh* __restrict__ Ch, fh* __restrict__ Cl,
                  float* __restrict__ Cf, size_t cHead, int ldc) {
    extern __shared__ char smem[];
    const uint32_t sb = smem_u32(smem);
    const int tid = threadIdx.x, wid = tid >> 5, lane = tid & 31;
    const int h = blockIdx.z;
    const int m0 = blockIdx.x * 128;
    const int n0 = blockIdx.y * 128;

    // stage layout: Ah[128][128B] Al Bh -> 48KB per stage, 2 stages
    constexpr uint32_t TILE = 128 * 128;       // 16KB
    constexpr uint32_t STAGE = 3 * TILE;       // 48KB

    const fh* gAh = Ah + h * aHead + (size_t)m0 * lda;
    const fh* gAl = Al + h * aHead + (size_t)m0 * lda;
    const fh* gBh = Bh + h * bHead + (size_t)n0 * K;

    // warp tile: 64(M) x 32(N); warp grid 2 x 4
    const int wm = (wid & 1) * 64;
    const int wn = (wid >> 1) * 32;

    int arow[4], brow[2];
#pragma unroll
    for (int mi = 0; mi < 4; mi++) arow[mi] = wm + mi * 16 + (lane & 15);
#pragma unroll
    for (int bj = 0; bj < 2; bj++)
        brow[bj] = wn + bj * 16 + ((lane >> 3) & 1) * 8 + (lane & 7);
    const int hi16 = lane >> 4;

    float acc[4][4][4];
#pragma unroll
    for (int i = 0; i < 4; i++)
#pragma unroll
        for (int j = 0; j < 4; j++)
#pragma unroll
            for (int e = 0; e < 4; e++) acc[i][j][e] = 0.f;

    const int KT = K >> 6;

    // preload stage 0
    ldt<128>(sb, gAh, lda, tid);
    ldt<128>(sb + TILE, gAl, lda, tid);
    ldt<128>(sb + 2 * TILE, gBh, K, tid);
    asm volatile("cp.async.commit_group;" ::: "memory");

    for (int c = 0; c < KT; c++) {
        const uint32_t st = sb + (uint32_t)(c & 1) * STAGE;
        if (c + 1 < KT) {
            const uint32_t sn = sb + (uint32_t)((c + 1) & 1) * STAGE;
            const int k0 = (c + 1) * 64;
            ldt<128>(sn, gAh + k0, lda, tid);
            ldt<128>(sn + TILE, gAl + k0, lda, tid);
            ldt<128>(sn + 2 * TILE, gBh + k0, K, tid);
            asm volatile("cp.async.commit_group;" ::: "memory");
            asm volatile("cp.async.wait_group 1;" ::: "memory");
        } else {
            asm volatile("cp.async.wait_group 0;" ::: "memory");
        }
        __syncthreads();

#pragma unroll
        for (int s = 0; s < 4; s++) {
            uint32_t ahf[4][4], alf[4][4], bhf[2][4];
            const int c2 = s * 2 + hi16;
#pragma unroll
            for (int mi = 0; mi < 4; mi++) {
                const uint32_t ao = arow[mi] * 128 + ((c2 ^ (arow[mi] & 7)) << 4);
                ldsm4(ahf[mi], st + ao);
                ldsm4(alf[mi], st + TILE + ao);
            }
#pragma unroll
            for (int bj = 0; bj < 2; bj++) {
                const uint32_t bo = brow[bj] * 128 + ((c2 ^ (brow[bj] & 7)) << 4);
                ldsm4(bhf[bj], st + 2 * TILE + bo);
            }
            // term 1: Ah * Bh
#pragma unroll
            for (int mi = 0; mi < 4; mi++)
#pragma unroll
                for (int bj = 0; bj < 2; bj++) {
                    mma16816(acc[mi][2 * bj],     ahf[mi], bhf[bj][0], bhf[bj][2]);
                    mma16816(acc[mi][2 * bj + 1], ahf[mi], bhf[bj][1], bhf[bj][3]);
                }
            // term 2: Al * Bh
#pragma unroll
            for (int mi = 0; mi < 4; mi++)
#pragma unroll
                for (int bj = 0; bj < 2; bj++) {
                    mma16816(acc[mi][2 * bj],     alf[mi], bhf[bj][0], bhf[bj][2]);
                    mma16816(acc[mi][2 * bj + 1], alf[mi], bhf[bj][1], bhf[bj][3]);
                }
        }
        __syncthreads();
    }

    // ---------------- epilogue ----------------
    const int rbase = (lane >> 2);
    const int cbase = (lane & 3) * 2;

#pragma unroll
    for (int mi = 0; mi < 4; mi++) {
#pragma unroll
        for (int nj = 0; nj < 4; nj++) {
#pragma unroll
            for (int half = 0; half < 2; half++) {
                const size_t m = (size_t)m0 + wm + mi * 16 + rbase + half * 8;
                const int col = n0 + wn + nj * 8 + cbase;
                float v0 = acc[mi][nj][2 * half];
                float v1 = acc[mi][nj][2 * half + 1];
                if (MODE == 0) {
                    v0 = gelu_f(v0);
                    v1 = gelu_f(v1);
                    fh h0, l0, h1, l1;
                    split2h(v0, h0, l0);
                    split2h(v1, h1, l1);
                    *reinterpret_cast<uint32_t*>(Ch + h * cHead + m * ldc + col) =
                        packh(h0, h1);
                    *reinterpret_cast<uint32_t*>(Cl + h * cHead + m * ldc + col) =
                        packh(l0, l1);
                } else {
                    *reinterpret_cast<float2*>(Cf + h * cHead + m * ldc + col) =
                        make_float2(v0, v1);
                }
            }
        }
    }
}

// ---------------- RMSNorm + hi/lo split of x ----------------
__global__ void rms_split_kernel(const float* __restrict__ x, const float* __restrict__ g,
                                 fh* __restrict__ xh, fh* __restrict__ xl) {
    const int row = blockIdx.x, tid = threadIdx.x;
    const float4* xr = reinterpret_cast<const float4*>(x + (size_t)row * DTOT);
    float4 a = xr[tid], b = xr[tid + 256];
    float s = a.x * a.x + a.y * a.y + a.z * a.z + a.w * a.w +
              b.x * b.x + b.y * b.y + b.z * b.z + b.w * b.w;
#pragma unroll
    for (int o = 16; o; o >>= 1) s += __shfl_xor_sync(0xffffffffu, s, o);
    __shared__ float ws[8];
    __shared__ float srs;
    if ((tid & 31) == 0) ws[tid >> 5] = s;
    __syncthreads();
    if (tid == 0) {
        float t = 0.f;
#pragma unroll
        for (int i = 0; i < 8; i++) t += ws[i];
        srs = rsqrtf(t * (1.0f / DTOT) + 1.1920929e-7f);
    }
    __syncthreads();
    const float rs = srs;
    const float4* gr = reinterpret_cast<const float4*>(g);
    float4 ga = gr[tid], gb = gr[tid + 256];

    float va[8] = {a.x * rs * ga.x, a.y * rs * ga.y, a.z * rs * ga.z, a.w * rs * ga.w,
                   b.x * rs * gb.x, b.y * rs * gb.y, b.z * rs * gb.z, b.w * rs * gb.w};
    size_t base = (size_t)row * DTOT;
#pragma unroll
    for (int half = 0; half < 2; half++) {
        size_t o = base + (size_t)(tid + half * 256) * 4;
        uint32_t hp[2], lp[2];
#pragma unroll
        for (int j = 0; j < 2; j++) {
            fh h0, l0, h1, l1;
            split2h(va[half * 4 + 2 * j], h0, l0);
            split2h(va[half * 4 + 2 * j + 1], h1, l1);
            hp[j] = packh(h0, h1);
            lp[j] = packh(l0, l1);
        }
        *reinterpret_cast<uint2*>(xh + o) = make_uint2(hp[0], hp[1]);
        *reinterpret_cast<uint2*>(xl + o) = make_uint2(lp[0], lp[1]);
    }
}

// ---------------- weight transpose to fp16: W[h][K][N] -> O[h][N][K] ----------------
__global__ void wsplit_kernel(const float* __restrict__ W, int K, int N,
                              fh* __restrict__ Oh) {
    __shared__ float t[32][33];
    const int h = blockIdx.z;
    const int k0 = blockIdx.x * 32, n0 = blockIdx.y * 32;
    const int tx = threadIdx.x & 31, ty = threadIdx.x >> 5;
    const float* Wb = W + (size_t)h * K * N;
#pragma unroll
    for (int i = 0; i < 4; i++)
        t[ty + i * 8][tx] = Wb[(size_t)(k0 + ty + i * 8) * N + n0 + tx];
    __syncthreads();
#pragma unroll
    for (int i = 0; i < 4; i++) {
        int n = n0 + ty + i * 8, k = k0 + tx;
        size_t o = ((size_t)h * N + n) * K + k;
        Oh[o] = __float2half_rn(t[tx][ty + i * 8]);
    }
}

// ---------------- launch ----------------
extern "C" void kernel_launch(void* const* d_in, const int* in_sizes, int n_in,
                              void* d_out, int out_size) {
    const float* x  = (const float*)d_in[0];
    const float* g  = (const float*)d_in[1];
    const float* w0 = (const float*)d_in[2];
    const float* w1 = (const float*)d_in[3];
    const float* w2 = (const float*)d_in[4];
    const float* w3 = (const float*)d_in[5];
    float* out = (float*)d_out;

    fh *xh, *xl, *ah, *al, *bh, *bl, *pw0, *pw1, *pw2, *pw3;
    cudaGetSymbolAddress((void**)&xh, g_xh);
    cudaGetSymbolAddress((void**)&xl, g_xl);
    cudaGetSymbolAddress((void**)&ah, g_ah);
    cudaGetSymbolAddress((void**)&al, g_al);
    cudaGetSymbolAddress((void**)&bh, g_bh);
    cudaGetSymbolAddress((void**)&bl, g_bl);
    cudaGetSymbolAddress((void**)&pw0, g_w0);
    cudaGetSymbolAddress((void**)&pw1, g_w1);
    cudaGetSymbolAddress((void**)&pw2, g_w2);
    cudaGetSymbolAddress((void**)&pw3, g_w3);

    constexpr int SMEM = 2 * 3 * 128 * 128;  // 98304
    cudaFuncSetAttribute(hgemm_kernel<0>,
                         cudaFuncAttributeMaxDynamicSharedMemorySize, SMEM);
    cudaFuncSetAttribute(hgemm_kernel<1>,
                         cudaFuncAttributeMaxDynamicSharedMemorySize, SMEM);

    // prep
    rms_split_kernel<<<NTOK, 256>>>(x, g, xh, xl);
    wsplit_kernel<<<dim3(DHEAD / 32, HID / 32, NHEAD), 256>>>(w0, DHEAD, HID, pw0);
    wsplit_kernel<<<dim3(HID / 32, HID / 32, NHEAD), 256>>>(w1, HID, HID, pw1);
    wsplit_kernel<<<dim3(HID / 32, HID / 32, NHEAD), 256>>>(w2, HID, HID, pw2);
    wsplit_kernel<<<dim3(HID / 32, DHEAD / 32, NHEAD), 256>>>(w3, HID, DHEAD, pw3);

    const size_t actHead = (size_t)NTOK * HID;

    // L0: a = gelu( xn[:,h] @ w0[h] )
    hgemm_kernel<0><<<dim3(NTOK / 128, HID / 128, NHEAD), 256, SMEM>>>(
        xh, xl, (size_t)DHEAD, DTOT, pw0, (size_t)HID * DHEAD, DHEAD,
        ah, al, nullptr, actHead, HID);
    // L1: b = gelu( a @ w1[h] )
    hgemm_kernel<0><<<dim3(NTOK / 128, HID / 128, NHEAD), 256, SMEM>>>(
        ah, al, actHead, HID, pw1, (size_t)HID * HID, HID,
        bh, bl, nullptr, actHead, HID);
    // L2: a = gelu( b @ w2[h] )
    hgemm_kernel<0><<<dim3(NTOK / 128, HID / 128, NHEAD), 256, SMEM>>>(
        bh, bl, actHead, HID, pw2, (size_t)HID * HID, HID,
        ah, al, nullptr, actHead, HID);
    // L3: out[:,h] = a @ w3[h]   (fp32, no gelu)
    hgemm_kernel<1><<<dim3(NTOK / 128, DHEAD / 128, NHEAD), 256, SMEM>>>(
        ah, al, actHead, HID, pw3, (size_t)DHEAD * HID, HID,
        nullptr, nullptr, out, (size_t)DHEAD, DTOT);
}

// round 5
// speedup vs baseline: 4.5910x; 1.4411x over previous
#include <cuda_runtime.h>
#include <cuda_fp16.h>
#include <math.h>
#include <stdint.h>

#define NTOK  16384
#define NHEAD 16
#define DHEAD 128
#define HID   512
#define DTOT  2048

typedef __half fh;

// ---------------- scratch (device globals; no allocs allowed) ----------------
static __device__ fh g_xh[(size_t)NTOK * DTOT];
static __device__ fh g_xl[(size_t)NTOK * DTOT];
static __device__ fh g_ah[(size_t)NHEAD * NTOK * HID];
static __device__ fh g_al[(size_t)NHEAD * NTOK * HID];
static __device__ fh g_bh[(size_t)NHEAD * NTOK * HID];
static __device__ fh g_w0[(size_t)NHEAD * HID * DHEAD];
static __device__ fh g_w1[(size_t)NHEAD * HID * HID];
static __device__ fh g_w2[(size_t)NHEAD * HID * HID];
static __device__ fh g_w3[(size_t)NHEAD * DHEAD * HID];

// ---------------- helpers ----------------
__device__ __forceinline__ uint32_t smem_u32(const void* p) {
    uint32_t a;
    asm("{ .reg .u64 t; cvta.to.shared.u64 t, %1; cvt.u32.u64 %0, t; }"
        : "=r"(a) : "l"(p));
    return a;
}
__device__ __forceinline__ float gelu_f(float x) {
    return 0.5f * x * (1.0f + erff(x * 0.70710678118654752f));
}
__device__ __forceinline__ void split2h(float v, fh& hi, fh& lo) {
    hi = __float2half_rn(v);
    lo = __float2half_rn(v - __half2float(hi));
}
__device__ __forceinline__ uint32_t packh(fh a, fh b) {
    return (uint32_t)__half_as_ushort(a) | ((uint32_t)__half_as_ushort(b) << 16);
}

__device__ __forceinline__ void ldsm4(uint32_t (&r)[4], uint32_t addr) {
    asm volatile("ldmatrix.sync.aligned.m8n8.x4.shared.b16 {%0,%1,%2,%3}, [%4];"
                 : "=r"(r[0]), "=r"(r[1]), "=r"(r[2]), "=r"(r[3]) : "r"(addr));
}
__device__ __forceinline__ void mma16816(float (&d)[4], const uint32_t (&a)[4],
                                         uint32_t b0, uint32_t b1) {
    asm volatile(
        "mma.sync.aligned.m16n8k16.row.col.f32.f16.f16.f32 "
        "{%0,%1,%2,%3}, {%4,%5,%6,%7}, {%8,%9}, {%0,%1,%2,%3};"
        : "+f"(d[0]), "+f"(d[1]), "+f"(d[2]), "+f"(d[3])
        : "r"(a[0]), "r"(a[1]), "r"(a[2]), "r"(a[3]), "r"(b0), "r"(b1));
}

// cp.async 16B tile loader: ROWS x 64 fp16 (128B rows), XOR-8 chunk swizzle
template <int ROWS>
__device__ __forceinline__ void ldt(uint32_t sbase, const fh* g, int ldg_, int tid) {
#pragma unroll
    for (int q = tid; q < ROWS * 8; q += 256) {
        int r = q >> 3, c8 = q & 7;
        uint32_t dst = sbase + r * 128 + ((c8 ^ (r & 7)) << 4);
        const char* src = (const char*)(g + (size_t)r * ldg_) + c8 * 16;
        asm volatile("cp.async.cg.shared.global [%0], [%1], 16;"
                     :: "r"(dst), "l"(src) : "memory");
    }
}

// =======================================================================
// HMMA fp16 GEMM: D[128x128] = (Ahi [+ Alo])[128xK] @ Bh[128xK]^T
// NTERMS: 1 = single-term A (hi only), 2 = hi+lo split A.
// OMODE:  0 = gelu -> split -> (Ch, Cl) fp16
//         1 = raw fp32 -> Cf
//         2 = gelu -> fp16 hi only -> Ch
// grid = (M/128, N/128, NHEAD), 256 threads, 2 CTAs/SM.
// =======================================================================
template <int NTERMS, int OMODE>
__global__ __launch_bounds__(256, 2)
void hgemm_kernel(const fh* __restrict__ Ah, const fh* __restrict__ Al,
                  size_t aHead, int lda,
                  const fh* __restrict__ Bh, size_t bHead, int K,
                  fh* __restrict__ Ch, fh* __restrict__ Cl,
                  float* __restrict__ Cf, size_t cHead, int ldc) {
    extern __shared__ char smem[];
    const uint32_t sb = smem_u32(smem);
    const int tid = threadIdx.x, wid = tid >> 5, lane = tid & 31;
    const int h = blockIdx.z;
    const int m0 = blockIdx.x * 128;
    const int n0 = blockIdx.y * 128;

    constexpr uint32_t TILE = 128 * 128;               // 16KB
    constexpr uint32_t STAGE = (NTERMS + 1) * TILE;    // 32 or 48 KB
    const uint32_t bOff = NTERMS * TILE;               // B tile offset in stage

    const fh* gAh = Ah + h * aHead + (size_t)m0 * lda;
    const fh* gAl = (NTERMS == 2) ? (Al + h * aHead + (size_t)m0 * lda) : nullptr;
    const fh* gBh = Bh + h * bHead + (size_t)n0 * K;

    // warp tile: 64(M) x 32(N); warp grid 2 x 4
    const int wm = (wid & 1) * 64;
    const int wn = (wid >> 1) * 32;

    int arow[4], brow[2];
#pragma unroll
    for (int mi = 0; mi < 4; mi++) arow[mi] = wm + mi * 16 + (lane & 15);
#pragma unroll
    for (int bj = 0; bj < 2; bj++)
        brow[bj] = wn + bj * 16 + ((lane >> 3) & 1) * 8 + (lane & 7);
    const int hi16 = lane >> 4;

    float acc[4][4][4];
#pragma unroll
    for (int i = 0; i < 4; i++)
#pragma unroll
        for (int j = 0; j < 4; j++)
#pragma unroll
            for (int e = 0; e < 4; e++) acc[i][j][e] = 0.f;

    const int KT = K >> 6;

    // preload stage 0
    ldt<128>(sb, gAh, lda, tid);
    if (NTERMS == 2) ldt<128>(sb + TILE, gAl, lda, tid);
    ldt<128>(sb + bOff, gBh, K, tid);
    asm volatile("cp.async.commit_group;" ::: "memory");

    for (int c = 0; c < KT; c++) {
        const uint32_t st = sb + (uint32_t)(c & 1) * STAGE;
        if (c + 1 < KT) {
            const uint32_t sn = sb + (uint32_t)((c + 1) & 1) * STAGE;
            const int k0 = (c + 1) * 64;
            ldt<128>(sn, gAh + k0, lda, tid);
            if (NTERMS == 2) ldt<128>(sn + TILE, gAl + k0, lda, tid);
            ldt<128>(sn + bOff, gBh + k0, K, tid);
            asm volatile("cp.async.commit_group;" ::: "memory");
            asm volatile("cp.async.wait_group 1;" ::: "memory");
        } else {
            asm volatile("cp.async.wait_group 0;" ::: "memory");
        }
        __syncthreads();

#pragma unroll
        for (int s = 0; s < 4; s++) {
            uint32_t ahf[4][4], alf[4][4], bhf[2][4];
            const int c2 = s * 2 + hi16;
#pragma unroll
            for (int mi = 0; mi < 4; mi++) {
                const uint32_t ao = arow[mi] * 128 + ((c2 ^ (arow[mi] & 7)) << 4);
                ldsm4(ahf[mi], st + ao);
                if (NTERMS == 2) ldsm4(alf[mi], st + TILE + ao);
            }
#pragma unroll
            for (int bj = 0; bj < 2; bj++) {
                const uint32_t bo = brow[bj] * 128 + ((c2 ^ (brow[bj] & 7)) << 4);
                ldsm4(bhf[bj], st + bOff + bo);
            }
            // term 1: Ah * Bh
#pragma unroll
            for (int mi = 0; mi < 4; mi++)
#pragma unroll
                for (int bj = 0; bj < 2; bj++) {
                    mma16816(acc[mi][2 * bj],     ahf[mi], bhf[bj][0], bhf[bj][2]);
                    mma16816(acc[mi][2 * bj + 1], ahf[mi], bhf[bj][1], bhf[bj][3]);
                }
            // term 2: Al * Bh
            if (NTERMS == 2) {
#pragma unroll
                for (int mi = 0; mi < 4; mi++)
#pragma unroll
                    for (int bj = 0; bj < 2; bj++) {
                        mma16816(acc[mi][2 * bj],     alf[mi], bhf[bj][0], bhf[bj][2]);
                        mma16816(acc[mi][2 * bj + 1], alf[mi], bhf[bj][1], bhf[bj][3]);
                    }
            }
        }
        __syncthreads();
    }

    // ---------------- epilogue ----------------
    const int rbase = (lane >> 2);
    const int cbase = (lane & 3) * 2;

#pragma unroll
    for (int mi = 0; mi < 4; mi++) {
#pragma unroll
        for (int nj = 0; nj < 4; nj++) {
#pragma unroll
            for (int half = 0; half < 2; half++) {
                const size_t m = (size_t)m0 + wm + mi * 16 + rbase + half * 8;
                const int col = n0 + wn + nj * 8 + cbase;
                float v0 = acc[mi][nj][2 * half];
                float v1 = acc[mi][nj][2 * half + 1];
                if (OMODE == 0) {
                    v0 = gelu_f(v0);
                    v1 = gelu_f(v1);
                    fh h0, l0, h1, l1;
                    split2h(v0, h0, l0);
                    split2h(v1, h1, l1);
                    *reinterpret_cast<uint32_t*>(Ch + h * cHead + m * ldc + col) =
                        packh(h0, h1);
                    *reinterpret_cast<uint32_t*>(Cl + h * cHead + m * ldc + col) =
                        packh(l0, l1);
                } else if (OMODE == 2) {
                    v0 = gelu_f(v0);
                    v1 = gelu_f(v1);
                    *reinterpret_cast<uint32_t*>(Ch + h * cHead + m * ldc + col) =
                        packh(__float2half_rn(v0), __float2half_rn(v1));
                } else {
                    *reinterpret_cast<float2*>(Cf + h * cHead + m * ldc + col) =
                        make_float2(v0, v1);
                }
            }
        }
    }
}

// ---------------- RMSNorm + hi/lo split of x ----------------
__global__ void rms_split_kernel(const float* __restrict__ x, const float* __restrict__ g,
                                 fh* __restrict__ xh, fh* __restrict__ xl) {
    const int row = blockIdx.x, tid = threadIdx.x;
    const float4* xr = reinterpret_cast<const float4*>(x + (size_t)row * DTOT);
    float4 a = xr[tid], b = xr[tid + 256];
    float s = a.x * a.x + a.y * a.y + a.z * a.z + a.w * a.w +
              b.x * b.x + b.y * b.y + b.z * b.z + b.w * b.w;
#pragma unroll
    for (int o = 16; o; o >>= 1) s += __shfl_xor_sync(0xffffffffu, s, o);
    __shared__ float ws[8];
    __shared__ float srs;
    if ((tid & 31) == 0) ws[tid >> 5] = s;
    __syncthreads();
    if (tid == 0) {
        float t = 0.f;
#pragma unroll
        for (int i = 0; i < 8; i++) t += ws[i];
        srs = rsqrtf(t * (1.0f / DTOT) + 1.1920929e-7f);
    }
    __syncthreads();
    const float rs = srs;
    const float4* gr = reinterpret_cast<const float4*>(g);
    float4 ga = gr[tid], gb = gr[tid + 256];

    float va[8] = {a.x * rs * ga.x, a.y * rs * ga.y, a.z * rs * ga.z, a.w * rs * ga.w,
                   b.x * rs * gb.x, b.y * rs * gb.y, b.z * rs * gb.z, b.w * rs * gb.w};
    size_t base = (size_t)row * DTOT;
#pragma unroll
    for (int half = 0; half < 2; half++) {
        size_t o = base + (size_t)(tid + half * 256) * 4;
        uint32_t hp[2], lp[2];
#pragma unroll
        for (int j = 0; j < 2; j++) {
            fh h0, l0, h1, l1;
            split2h(va[half * 4 + 2 * j], h0, l0);
            split2h(va[half * 4 + 2 * j + 1], h1, l1);
            hp[j] = packh(h0, h1);
            lp[j] = packh(l0, l1);
        }
        *reinterpret_cast<uint2*>(xh + o) = make_uint2(hp[0], hp[1]);
        *reinterpret_cast<uint2*>(xl + o) = make_uint2(lp[0], lp[1]);
    }
}

// ---------------- weight transpose to fp16: W[h][K][N] -> O[h][N][K] ----------------
__global__ void wsplit_kernel(const float* __restrict__ W, int K, int N,
                              fh* __restrict__ Oh) {
    __shared__ float t[32][33];
    const int h = blockIdx.z;
    const int k0 = blockIdx.x * 32, n0 = blockIdx.y * 32;
    const int tx = threadIdx.x & 31, ty = threadIdx.x >> 5;
    const float* Wb = W + (size_t)h * K * N;
#pragma unroll
    for (int i = 0; i < 4; i++)
        t[ty + i * 8][tx] = Wb[(size_t)(k0 + ty + i * 8) * N + n0 + tx];
    __syncthreads();
#pragma unroll
    for (int i = 0; i < 4; i++) {
        int n = n0 + ty + i * 8, k = k0 + tx;
        size_t o = ((size_t)h * N + n) * K + k;
        Oh[o] = __float2half_rn(t[tx][ty + i * 8]);
    }
}

// ---------------- launch ----------------
extern "C" void kernel_launch(void* const* d_in, const int* in_sizes, int n_in,
                              void* d_out, int out_size) {
    const float* x  = (const float*)d_in[0];
    const float* g  = (const float*)d_in[1];
    const float* w0 = (const float*)d_in[2];
    const float* w1 = (const float*)d_in[3];
    const float* w2 = (const float*)d_in[4];
    const float* w3 = (const float*)d_in[5];
    float* out = (float*)d_out;

    fh *xh, *xl, *ah, *al, *bh, *pw0, *pw1, *pw2, *pw3;
    cudaGetSymbolAddress((void**)&xh, g_xh);
    cudaGetSymbolAddress((void**)&xl, g_xl);
    cudaGetSymbolAddress((void**)&ah, g_ah);
    cudaGetSymbolAddress((void**)&al, g_al);
    cudaGetSymbolAddress((void**)&bh, g_bh);
    cudaGetSymbolAddress((void**)&pw0, g_w0);
    cudaGetSymbolAddress((void**)&pw1, g_w1);
    cudaGetSymbolAddress((void**)&pw2, g_w2);
    cudaGetSymbolAddress((void**)&pw3, g_w3);

    constexpr int SMEM2 = 2 * 3 * 128 * 128;  // 96KB: 2-term stages
    constexpr int SMEM1 = 2 * 2 * 128 * 128;  // 64KB: 1-term stages
    cudaFuncSetAttribute(hgemm_kernel<2, 2>,
                         cudaFuncAttributeMaxDynamicSharedMemorySize, SMEM2);
    cudaFuncSetAttribute(hgemm_kernel<1, 2>,
                         cudaFuncAttributeMaxDynamicSharedMemorySize, SMEM1);
    cudaFuncSetAttribute(hgemm_kernel<1, 0>,
                         cudaFuncAttributeMaxDynamicSharedMemorySize, SMEM1);
    cudaFuncSetAttribute(hgemm_kernel<2, 1>,
                         cudaFuncAttributeMaxDynamicSharedMemorySize, SMEM2);

    // prep
    rms_split_kernel<<<NTOK, 256>>>(x, g, xh, xl);
    wsplit_kernel<<<dim3(DHEAD / 32, HID / 32, NHEAD), 256>>>(w0, DHEAD, HID, pw0);
    wsplit_kernel<<<dim3(HID / 32, HID / 32, NHEAD), 256>>>(w1, HID, HID, pw1);
    wsplit_kernel<<<dim3(HID / 32, HID / 32, NHEAD), 256>>>(w2, HID, HID, pw2);
    wsplit_kernel<<<dim3(HID / 32, DHEAD / 32, NHEAD), 256>>>(w3, HID, DHEAD, pw3);

    const size_t actHead = (size_t)NTOK * HID;

    // L0: a = gelu( xn[:,h] @ w0[h] )   2-term in, hi-only out (L1 is 1-term)
    hgemm_kernel<2, 2><<<dim3(NTOK / 128, HID / 128, NHEAD), 256, SMEM2>>>(
        xh, xl, (size_t)DHEAD, DTOT, pw0, (size_t)HID * DHEAD, DHEAD,
        ah, nullptr, nullptr, actHead, HID);
    // L1: b = gelu( a @ w1[h] )         1-term in, hi-only out (L2 is 1-term)
    hgemm_kernel<1, 2><<<dim3(NTOK / 128, HID / 128, NHEAD), 256, SMEM1>>>(
        ah, nullptr, actHead, HID, pw1, (size_t)HID * HID, HID,
        bh, nullptr, nullptr, actHead, HID);
    // L2: a = gelu( b @ w2[h] )         1-term in, split out (L3 is 2-term)
    hgemm_kernel<1, 0><<<dim3(NTOK / 128, HID / 128, NHEAD), 256, SMEM1>>>(
        bh, nullptr, actHead, HID, pw2, (size_t)HID * HID, HID,
        ah, al, nullptr, actHead, HID);
    // L3: out[:,h] = a @ w3[h]          2-term in, fp32 out, no gelu
    hgemm_kernel<2, 1><<<dim3(NTOK / 128, DHEAD / 128, NHEAD), 256, SMEM2>>>(
        ah, al, actHead, HID, pw3, (size_t)DHEAD * HID, HID,
        nullptr, nullptr, out, (size_t)DHEAD, DTOT);
}